// round 1
// baseline (speedup 1.0000x reference)
#include <cuda_runtime.h>
#include <math.h>

#define BZ 8
#define LQ 1024
#define D  512
#define NH 8
#define DH 64

// ---------------- scratch (device globals; no allocation allowed) ----------------
__device__ float g_h[BZ * LQ * D];        // 16 MB  h = transpose(query) [bz, Lq, d]
__device__ float g_Q[BZ * LQ * D];        // 16 MB
__device__ float g_K[BZ * LQ * D];        // 16 MB
__device__ float g_V[BZ * LQ * D];        // 16 MB
__device__ float g_norm[BZ * LQ];         // row norms of h (clamped at 1e-8)
__device__ unsigned char g_mask[(size_t)BZ * LQ * LQ];  // 8 MB, 1 = masked

// ---------------- K1: transpose query[Lq,bz,d] -> h[bz,Lq,d] ----------------
__global__ void k_transpose(const float* __restrict__ q) {
    int idx = blockIdx.x * blockDim.x + threadIdx.x;      // float4 index
    if (idx >= BZ * LQ * (D / 4)) return;
    int k4 = idx & 127;               // D/4 = 128
    int b  = (idx >> 7) & 7;
    int i  = idx >> 10;
    float4 v = ((const float4*)q)[idx];                   // [(i*8+b)*128 + k4] == idx
    ((float4*)g_h)[(b * LQ + i) * (D / 4) + k4] = v;
}

// ---------------- K2: per-row norms of h ----------------
__global__ void k_norms() {
    int warp = (blockIdx.x * blockDim.x + threadIdx.x) >> 5;
    int lane = threadIdx.x & 31;
    if (warp >= BZ * LQ) return;
    const float* row = g_h + (size_t)warp * D;
    float s = 0.f;
    for (int k = lane; k < D; k += 32) { float v = row[k]; s += v * v; }
    #pragma unroll
    for (int o = 16; o; o >>= 1) s += __shfl_xor_sync(0xffffffffu, s, o);
    if (lane == 0) g_norm[warp] = fmaxf(sqrtf(s), 1e-8f);
}

// ---------------- K3: C[M,N] = A[M,K] * B[N,K]^T + bias[N] ----------------
// 64x64 tile per block, 256 threads (16x16), 4x4 micro-tile, k-panel 16.
__global__ __launch_bounds__(256) void k_sgemm_nt(
    const float* __restrict__ A, const float* __restrict__ B,
    const float* __restrict__ bias, float* __restrict__ C,
    int M, int N, int K)
{
    __shared__ float As[16][65];
    __shared__ float Bs[16][65];
    int tx = threadIdx.x & 15, ty = threadIdx.x >> 4;
    int m0 = blockIdx.y * 64, n0 = blockIdx.x * 64;
    float acc[4][4] = {};
    for (int k0 = 0; k0 < K; k0 += 16) {
        for (int t = threadIdx.x; t < 1024; t += 256) {
            int kk = t & 15, r = t >> 4;
            As[kk][r] = A[(size_t)(m0 + r) * K + k0 + kk];
            Bs[kk][r] = B[(size_t)(n0 + r) * K + k0 + kk];
        }
        __syncthreads();
        #pragma unroll
        for (int kk = 0; kk < 16; kk++) {
            float a[4], bb[4];
            #pragma unroll
            for (int i = 0; i < 4; i++) a[i] = As[kk][ty + 16 * i];
            #pragma unroll
            for (int j = 0; j < 4; j++) bb[j] = Bs[kk][tx + 16 * j];
            #pragma unroll
            for (int i = 0; i < 4; i++)
                #pragma unroll
                for (int j = 0; j < 4; j++) acc[i][j] += a[i] * bb[j];
        }
        __syncthreads();
    }
    #pragma unroll
    for (int i = 0; i < 4; i++)
        #pragma unroll
        for (int j = 0; j < 4; j++) {
            int m = m0 + ty + 16 * i, n = n0 + tx + 16 * j;
            C[(size_t)m * N + n] = acc[i][j] + bias[n];
        }
}

// ---------------- K4: mask = f(iou(segments), cos(h,h)) ----------------
// Gram GEMM h_b @ h_b^T with fused mask epilogue. Grid (Lq/64, Lq/64, bz).
__global__ __launch_bounds__(256) void k_mask(const float* __restrict__ seg) {
    __shared__ float As[16][65], Bs[16][65];
    __shared__ float si[64], ei[64], li[64], ni[64];
    __shared__ float sj[64], ej[64], lj[64], nj[64];
    int b  = blockIdx.z;
    int i0 = blockIdx.y * 64, j0 = blockIdx.x * 64;
    int tid = threadIdx.x, tx = tid & 15, ty = tid >> 4;

    if (tid < 64) {
        int gi = b * LQ + i0 + tid;
        float c = seg[gi * 2], l = seg[gi * 2 + 1];
        si[tid] = c - 0.5f * l; ei[tid] = c + 0.5f * l; li[tid] = l;
        ni[tid] = g_norm[gi];
    } else if (tid < 128) {
        int t = tid - 64;
        int gj = b * LQ + j0 + t;
        float c = seg[gj * 2], l = seg[gj * 2 + 1];
        sj[t] = c - 0.5f * l; ej[t] = c + 0.5f * l; lj[t] = l;
        nj[t] = g_norm[gj];
    }

    const float* A = g_h + (size_t)b * LQ * D;
    float acc[4][4] = {};
    for (int k0 = 0; k0 < D; k0 += 16) {
        for (int t = tid; t < 1024; t += 256) {
            int kk = t & 15, r = t >> 4;
            As[kk][r] = A[(size_t)(i0 + r) * D + k0 + kk];
            Bs[kk][r] = A[(size_t)(j0 + r) * D + k0 + kk];
        }
        __syncthreads();
        #pragma unroll
        for (int kk = 0; kk < 16; kk++) {
            float a[4], bb[4];
            #pragma unroll
            for (int i = 0; i < 4; i++) a[i] = As[kk][ty + 16 * i];
            #pragma unroll
            for (int j = 0; j < 4; j++) bb[j] = Bs[kk][tx + 16 * j];
            #pragma unroll
            for (int i = 0; i < 4; i++)
                #pragma unroll
                for (int j = 0; j < 4; j++) acc[i][j] += a[i] * bb[j];
        }
        __syncthreads();
    }
    #pragma unroll
    for (int i = 0; i < 4; i++)
        #pragma unroll
        for (int j = 0; j < 4; j++) {
            int ii = ty + 16 * i, jj = tx + 16 * j;
            float cosv  = acc[i][j] / (ni[ii] * nj[jj]);
            float inter = fmaxf(fminf(ei[ii], ej[jj]) - fmaxf(si[ii], sj[jj]), 0.f);
            float uni   = li[ii] + lj[jj] - inter;
            float iou   = inter / uni;
            int gi = i0 + ii, gj = j0 + jj;
            bool masked = (cosv <= 0.2f) || (iou > 0.2f && gi != gj);
            g_mask[((size_t)b * LQ + gi) * LQ + gj] = masked ? 1 : 0;
        }
}

// ---------------- K5: flash attention + residual + output transpose ----------------
// Grid (Lq/64, NH, bz). 256 threads. Online softmax with -1e30 sentinel
// (diagonal is always unmasked so every row eventually gets a real max;
// junk accumulated while row-max == -1e30 is wiped by the exp-rescale).
#define SMF (64 * 65)
__global__ __launch_bounds__(256) void k_attn(float* __restrict__ out) {
    extern __shared__ float sm[];
    float* Qs   = sm;
    float* Kst  = Qs  + SMF;   // K transposed: Kst[k][c]
    float* Vs   = Kst + SMF;   // Vs[c][k]
    float* Ss   = Vs  + SMF;   // scores / probabilities
    float* mrow = Ss  + SMF;
    float* lrow = mrow + 64;
    float* srow = lrow + 64;

    int i0 = blockIdx.x * 64, head = blockIdx.y, b = blockIdx.z;
    int tid = threadIdx.x, tx = tid & 15, ty = tid >> 4;
    const size_t base = (size_t)b * LQ * D + head * DH;

    for (int t = tid; t < 64 * 64; t += 256) {
        int r = t >> 6, k = t & 63;
        Qs[r * 65 + k] = g_Q[base + (size_t)(i0 + r) * D + k];
    }
    if (tid < 64) { mrow[tid] = -1e30f; lrow[tid] = 0.f; }
    float O[4][4] = {};
    __syncthreads();

    for (int j0 = 0; j0 < LQ; j0 += 64) {
        for (int t = tid; t < 64 * 64; t += 256) {
            int c = t >> 6, k = t & 63;
            Kst[k * 65 + c] = g_K[base + (size_t)(j0 + c) * D + k];
            Vs [c * 65 + k] = g_V[base + (size_t)(j0 + c) * D + k];
        }
        __syncthreads();

        // S = Q K^T / 8, masked
        float acc[4][4] = {};
        #pragma unroll 4
        for (int k = 0; k < 64; k++) {
            float a[4], bb[4];
            #pragma unroll
            for (int i = 0; i < 4; i++) a[i] = Qs[(ty + 16 * i) * 65 + k];
            #pragma unroll
            for (int j = 0; j < 4; j++) bb[j] = Kst[k * 65 + tx + 16 * j];
            #pragma unroll
            for (int i = 0; i < 4; i++)
                #pragma unroll
                for (int j = 0; j < 4; j++) acc[i][j] += a[i] * bb[j];
        }
        const unsigned char* mp = g_mask + ((size_t)b * LQ + i0) * LQ + j0;
        #pragma unroll
        for (int i = 0; i < 4; i++)
            #pragma unroll
            for (int j = 0; j < 4; j++) {
                int ii = ty + 16 * i, jj = tx + 16 * j;
                bool msk = mp[(size_t)ii * LQ + jj];
                Ss[ii * 65 + jj] = msk ? -1e30f : acc[i][j] * 0.125f;
            }
        __syncthreads();

        // online softmax (one thread per row)
        if (tid < 64) {
            float m_old = mrow[tid], mx = m_old;
            float* srp = Ss + tid * 65;
            #pragma unroll 8
            for (int c = 0; c < 64; c++) mx = fmaxf(mx, srp[c]);
            float sc = __expf(m_old - mx);
            float sum = 0.f;
            #pragma unroll 8
            for (int c = 0; c < 64; c++) {
                float p = __expf(srp[c] - mx);
                srp[c] = p;
                sum += p;
            }
            lrow[tid] = lrow[tid] * sc + sum;
            mrow[tid] = mx;
            srow[tid] = sc;
        }
        __syncthreads();

        // rescale O, accumulate P @ V
        float scs[4];
        #pragma unroll
        for (int i = 0; i < 4; i++) scs[i] = srow[ty + 16 * i];
        #pragma unroll
        for (int i = 0; i < 4; i++)
            #pragma unroll
            for (int j = 0; j < 4; j++) O[i][j] *= scs[i];
        #pragma unroll 4
        for (int jj = 0; jj < 64; jj++) {
            float p[4], v[4];
            #pragma unroll
            for (int i = 0; i < 4; i++) p[i] = Ss[(ty + 16 * i) * 65 + jj];
            #pragma unroll
            for (int j = 0; j < 4; j++) v[j] = Vs[jj * 65 + tx + 16 * j];
            #pragma unroll
            for (int i = 0; i < 4; i++)
                #pragma unroll
                for (int j = 0; j < 4; j++) O[i][j] += p[i] * v[j];
        }
        __syncthreads();
    }

    // epilogue: out[Lq, bz, d] = O/l + h
    #pragma unroll
    for (int i = 0; i < 4; i++) {
        int ii = ty + 16 * i, gi = i0 + ii;
        float inv_l = 1.f / lrow[ii];
        #pragma unroll
        for (int j = 0; j < 4; j++) {
            int c = tx + 16 * j;
            float hv = g_h[((size_t)b * LQ + gi) * D + head * DH + c];
            out[((size_t)gi * BZ + b) * D + head * DH + c] = O[i][j] * inv_l + hv;
        }
    }
}

// ---------------- host ----------------
extern "C" void kernel_launch(void* const* d_in, const int* in_sizes, int n_in,
                              void* d_out, int out_size) {
    const float* query = (const float*)d_in[0];
    const float* seg   = (const float*)d_in[1];
    const float* Wq    = (const float*)d_in[2];
    const float* bq    = (const float*)d_in[3];
    const float* Wk    = (const float*)d_in[4];
    const float* bk    = (const float*)d_in[5];
    const float* Wv    = (const float*)d_in[6];
    const float* bv    = (const float*)d_in[7];
    float* out = (float*)d_out;

    float *hp, *qp, *kp, *vp;
    cudaGetSymbolAddress((void**)&hp, g_h);
    cudaGetSymbolAddress((void**)&qp, g_Q);
    cudaGetSymbolAddress((void**)&kp, g_K);
    cudaGetSymbolAddress((void**)&vp, g_V);

    k_transpose<<<(BZ * LQ * (D / 4) + 255) / 256, 256>>>(query);
    k_norms<<<(BZ * LQ * 32) / 256, 256>>>();

    dim3 gg(D / 64, BZ * LQ / 64);   // (8, 128)
    k_sgemm_nt<<<gg, 256>>>(hp, Wq, bq, qp, BZ * LQ, D, D);
    k_sgemm_nt<<<gg, 256>>>(hp, Wk, bk, kp, BZ * LQ, D, D);
    k_sgemm_nt<<<gg, 256>>>(hp, Wv, bv, vp, BZ * LQ, D, D);

    dim3 gm(LQ / 64, LQ / 64, BZ);   // (16, 16, 8)
    k_mask<<<gm, 256>>>(seg);

    int smem = (4 * SMF + 3 * 64) * (int)sizeof(float);  // ~67.3 KB
    cudaFuncSetAttribute(k_attn, cudaFuncAttributeMaxDynamicSharedMemorySize, smem);
    dim3 ga(LQ / 64, NH, BZ);        // (16, 8, 8)
    k_attn<<<ga, 256, smem>>>(out);
}